// round 6
// baseline (speedup 1.0000x reference)
#include <cuda_runtime.h>
#include <cuda_bf16.h>
#include <cstdint>

#define N_ROIS 250000
#define G      128
#define NTOT   (N_ROIS + G)      // 250128 (< 2^18)
#define NBK    4096
#define CAP    320
#define RPT    4                 // ROIs per thread in k_iou
#define TB     256               // threads per block in k_iou

// ---------------- scratch (device globals; no allocation) ----------------
__device__ unsigned            g_bcnt[2][NBK];
__device__ unsigned long long  g_bucket[2][NBK * CAP];   // ~21 MB
// g_bcnt zeroed at tail of k_select for next replay; zero-init covers call #1.

// ---------------- threefry2x32 with key (0, 42) ----------------
__device__ __forceinline__ uint2 threefry42(unsigned x0, unsigned x1) {
    const unsigned ks0 = 0u;
    const unsigned ks1 = 42u;
    const unsigned ks2 = 0x1BD11BDAu ^ ks0 ^ ks1;
#define TF_ROUND(r) { x0 += x1; x1 = (x1 << (r)) | (x1 >> (32 - (r))); x1 ^= x0; }
    x0 += ks0; x1 += ks1;
    TF_ROUND(13) TF_ROUND(15) TF_ROUND(26) TF_ROUND(6)
    x0 += ks1; x1 += ks2 + 1u;
    TF_ROUND(17) TF_ROUND(29) TF_ROUND(16) TF_ROUND(24)
    x0 += ks2; x1 += ks0 + 2u;
    TF_ROUND(13) TF_ROUND(15) TF_ROUND(26) TF_ROUND(6)
    x0 += ks0; x1 += ks1 + 3u;
    TF_ROUND(17) TF_ROUND(29) TF_ROUND(16) TF_ROUND(24)
    x0 += ks1; x1 += ks2 + 4u;
    TF_ROUND(13) TF_ROUND(15) TF_ROUND(26) TF_ROUND(6)
    x0 += ks2; x1 += ks0 + 5u;
#undef TF_ROUND
    return make_uint2(x0, x1);
}

// ---------------- K1: IoU max/argmax + key + bucket append ----------------
__global__ void __launch_bounds__(TB) k_iou(const float* __restrict__ rois,
                                            const float* __restrict__ gtb) {
    __shared__ float4 sb[G];   // x1,y1,x2,y2
    __shared__ float  sa[G];   // area_b
    int tid = threadIdx.x;
    if (tid < G) {
        float x1 = gtb[tid * 4 + 0], y1 = gtb[tid * 4 + 1];
        float x2 = gtb[tid * 4 + 2], y2 = gtb[tid * 4 + 3];
        sb[tid] = make_float4(x1, y1, x2, y2);
        sa[tid] = __fmul_rn(x2 - x1 + 1.0f, y2 - y1 + 1.0f);
    }
    __syncthreads();

    int base = blockIdx.x * (TB * RPT) + tid;

    float ax1[RPT], ay1[RPT], ax2[RPT], ay2[RPT], aa[RPT], bn[RPT], bs[RPT];
    int bj[RPT];
#pragma unroll
    for (int r = 0; r < RPT; r++) {
        int i = base + r * TB;
        int ii = (i < NTOT) ? i : 0;
        if (ii < N_ROIS) {
            const float* p = rois + (size_t)ii * 5;
            ax1[r] = p[1]; ay1[r] = p[2]; ax2[r] = p[3]; ay2[r] = p[4];
        } else {
            const float* p = gtb + (size_t)(ii - N_ROIS) * 4;
            ax1[r] = p[0]; ay1[r] = p[1]; ax2[r] = p[2]; ay2[r] = p[3];
        }
        aa[r] = __fmul_rn(ax2[r] - ax1[r] + 1.0f, ay2[r] - ay1[r] + 1.0f);
        bn[r] = 0.0f; bs[r] = 1.0f; bj[r] = 0;
    }

#pragma unroll 4
    for (int j = 0; j < G; j++) {
        float4 b = sb[j];
        float  ab = sa[j];
#pragma unroll
        for (int r = 0; r < RPT; r++) {
            float xx1 = fmaxf(ax1[r], b.x);
            float yy1 = fmaxf(ay1[r], b.y);
            float xx2 = fminf(ax2[r], b.z);
            float yy2 = fminf(ay2[r], b.w);
            float iw = fmaxf(xx2 - xx1 + 1.0f, 0.0f);
            float ih = fmaxf(yy2 - yy1 + 1.0f, 0.0f);
            float inter = __fmul_rn(iw, ih);
            float S = aa[r] + ab;   // area_a + area_b (same rounding as reference)
            // iou ordering: inter/(S-inter) ordering == inter/S ordering (exact, S>0)
            if (__fmul_rn(inter, bs[r]) > __fmul_rn(bn[r], S)) {
                bn[r] = inter; bs[r] = S; bj[r] = j;
            }
        }
    }

#pragma unroll
    for (int r = 0; r < RPT; r++) {
        int i = base + r * TB;
        if (i >= NTOT) continue;
        // max overlap with reference rounding: denom = (area_a+area_b) - inter
        float mov = __fdiv_rn(bn[r], bs[r] - bn[r]);
        bool fg = (mov >= 0.5f);
        bool bg = (mov < 0.5f) && (mov >= 0.1f);
        if (fg || bg) {
            uint2 y = threefry42(0u, (unsigned)i);
            unsigned m = ((y.x ^ y.y) >> 9) + 1u;   // 1 .. 2^23, monotone in u
            unsigned long long rec =
                ((unsigned long long)m << 25) |
                ((unsigned long long)(0x3FFFFu - (unsigned)i) << 7) |
                (unsigned long long)(unsigned)bj[r];
            int sel = fg ? 0 : 1;
            unsigned bb = (m - 1u) >> 11;                 // 0..4095
            unsigned p = atomicAdd(&g_bcnt[sel][bb], 1u);
            if (p < CAP) g_bucket[sel][bb * CAP + p] = rec;
        }
    }
}

// ---------------- K2: select top-128, sort, and write ALL outputs ----------------
__global__ void __launch_bounds__(512) k_select(const float* __restrict__ rois,
                                                const float* __restrict__ gtb,
                                                const int* __restrict__ gtl,
                                                float* __restrict__ out) {
    __shared__ unsigned           schunk[512];
    __shared__ unsigned long long skey[512];
    __shared__ int                sB;
    __shared__ int                s_lab[128];
    __shared__ float              s_tgt[128][4];
    int sel = blockIdx.x;
    int t = threadIdx.x;

    unsigned loc[8];
    unsigned csum = 0;
#pragma unroll
    for (int k = 0; k < 8; k++) { loc[k] = g_bcnt[sel][t * 8 + k]; csum += loc[k]; }
    schunk[t] = csum;
    if (t == 0) sB = 0;
    __syncthreads();

    // suffix scan (inclusive from top) over 512 chunk sums
    for (int off = 1; off < 512; off <<= 1) {
        unsigned v = schunk[t];
        unsigned add = (t + off < 512) ? schunk[t + off] : 0u;
        __syncthreads();
        schunk[t] = v + add;
        __syncthreads();
    }
    unsigned ex = schunk[t] - csum;   // sum over chunks strictly above mine

    // per-bin inclusive-from-top cumulative C
    unsigned Carr[8];
    {
        unsigned suf = 0;
#pragma unroll
        for (int k = 7; k >= 0; k--) { suf += loc[k]; Carr[k] = ex + suf; }
    }
#pragma unroll
    for (int k = 0; k < 8; k++)
        if (Carr[k] >= 128u) atomicMax(&sB, t * 8 + k);
    skey[t] = 0ull;
    __syncthreads();
    int B = sB;   // highest bin whose inclusive-from-top count reaches 128

    // gather entries from bins >= B into compact shared array (expected ~190)
#pragma unroll
    for (int k = 0; k < 8; k++) {
        int bin = t * 8 + k;
        if (bin >= B && loc[k] > 0) {
            unsigned cnt = loc[k] < CAP ? loc[k] : CAP;
            unsigned off = Carr[k] - loc[k];   // entries in bins above this one
            for (unsigned e = 0; e < cnt; e++) {
                unsigned pos = off + e;
                if (pos < 512) skey[pos] = g_bucket[sel][bin * CAP + e];
            }
        }
    }
    __syncthreads();

    // bitonic sort 512 u64 ascending (1 element per thread)
    for (unsigned k = 2; k <= 512; k <<= 1) {
        for (unsigned j = k >> 1; j > 0; j >>= 1) {
            unsigned ixj = (unsigned)t ^ j;
            if (ixj > (unsigned)t) {
                bool up = ((t & k) == 0);
                unsigned long long a = skey[t], b = skey[ixj];
                if (up ? (a > b) : (a < b)) { skey[t] = b; skey[ixj] = a; }
            }
            __syncthreads();
        }
    }

    // ---- epilogue: rows, labels, targets (threads 0..127) ----
    if (t < 128) {
        unsigned long long rec = skey[511 - t];   // rank t (descending key, idx tiebreak)
        unsigned idx = 0x3FFFFu - (unsigned)((rec >> 7) & 0x3FFFFu);
        int ga = (int)(rec & 0x7Fu);
        if (idx >= NTOT) { idx = 0; ga = 0; }

        float c0, x1, y1, x2, y2;
        if (idx < N_ROIS) {
            const float* p = rois + (size_t)idx * 5;
            c0 = p[0]; x1 = p[1]; y1 = p[2]; x2 = p[3]; y2 = p[4];
        } else {
            const float* p = gtb + (size_t)(idx - N_ROIS) * 4;
            c0 = 0.0f; x1 = p[0]; y1 = p[1]; x2 = p[2]; y2 = p[3];
        }

        int rg = sel * 128 + t;   // global row 0..255
        // fg half: valid_fg always true (gt self-match guarantees >=128 fg)
        int label = (sel == 0) ? gtl[ga] : 0;
        s_lab[t] = label;

        out[rg * 5 + 0] = c0;
        out[rg * 5 + 1] = x1;
        out[rg * 5 + 2] = y1;
        out[rg * 5 + 3] = x2;
        out[rg * 5 + 4] = y2;
        out[1280 + rg] = (float)label;

        const float* g = gtb + (size_t)ga * 4;
        float ew = x2 - x1 + 1.0f, eh = y2 - y1 + 1.0f;
        float ecx = x1 + 0.5f * ew, ecy = y1 + 0.5f * eh;
        float gw = g[2] - g[0] + 1.0f, gh = g[3] - g[1] + 1.0f;
        float gcx = g[0] + 0.5f * gw, gcy = g[1] + 0.5f * gh;
        s_tgt[t][0] = (gcx - ecx) / ew;
        s_tgt[t][1] = (gcy - ecy) / eh;
        s_tgt[t][2] = logf(gw / ew);
        s_tgt[t][3] = logf(gh / eh);
    }
    __syncthreads();

    // ---- bbox_targets slab for this block's 128 rows: coalesced fill ----
    float* slab = out + 1536 + (size_t)sel * 128 * 84;
    for (int e = t; e < 128 * 84; e += 512) {
        int row = e / 84;
        int col = e - row * 84;
        int lab = s_lab[row];
        float v = 0.0f;
        int c0 = lab * 4;
        if (lab > 0 && col >= c0 && col < c0 + 4)
            v = s_tgt[row][col - c0];
        slab[e] = v;
    }

    // ---- re-zero this selector's bucket counters for the next replay ----
#pragma unroll
    for (int k = 0; k < 8; k++) g_bcnt[sel][t * 8 + k] = 0u;
}

// ---------------- launch ----------------
extern "C" void kernel_launch(void* const* d_in, const int* in_sizes, int n_in,
                              void* d_out, int out_size) {
    const float* all_rois = nullptr;  // 1,250,000 elems
    const float* gtb      = nullptr;  // 512 elems
    const int*   gtl      = nullptr;  // 128 elems
    for (int k = 0; k < n_in; k++) {
        if (in_sizes[k] == N_ROIS * 5) all_rois = (const float*)d_in[k];
        else if (in_sizes[k] == G * 4) gtb = (const float*)d_in[k];
        else if (in_sizes[k] == G)     gtl = (const int*)d_in[k];
    }
    float* out = (float*)d_out;

    k_iou<<<(NTOT + TB * RPT - 1) / (TB * RPT), TB>>>(all_rois, gtb);
    k_select<<<2, 512>>>(all_rois, gtb, gtl, out);
}

// round 7
// speedup vs baseline: 1.1567x; 1.1567x over previous
#include <cuda_runtime.h>
#include <cuda_bf16.h>
#include <cstdint>

#define N_ROIS 250000
#define G      128
#define NTOT   (N_ROIS + G)      // 250128 (< 2^18)
#define NBK    4096
#define CAP    320
#define RPT    4                 // ROIs per thread in k_iou
#define TB     512               // threads per block in k_iou -> grid=123, one wave

// ---------------- scratch (device globals; no allocation) ----------------
__device__ unsigned            g_bcnt[2][NBK];
__device__ unsigned long long  g_bucket[2][NBK * CAP];   // ~21 MB
// g_bcnt zeroed at tail of k_select for next replay; zero-init covers call #1.

// ---------------- threefry2x32 with key (0, 42) ----------------
__device__ __forceinline__ uint2 threefry42(unsigned x0, unsigned x1) {
    const unsigned ks0 = 0u;
    const unsigned ks1 = 42u;
    const unsigned ks2 = 0x1BD11BDAu ^ ks0 ^ ks1;
#define TF_ROUND(r) { x0 += x1; x1 = (x1 << (r)) | (x1 >> (32 - (r))); x1 ^= x0; }
    x0 += ks0; x1 += ks1;
    TF_ROUND(13) TF_ROUND(15) TF_ROUND(26) TF_ROUND(6)
    x0 += ks1; x1 += ks2 + 1u;
    TF_ROUND(17) TF_ROUND(29) TF_ROUND(16) TF_ROUND(24)
    x0 += ks2; x1 += ks0 + 2u;
    TF_ROUND(13) TF_ROUND(15) TF_ROUND(26) TF_ROUND(6)
    x0 += ks0; x1 += ks1 + 3u;
    TF_ROUND(17) TF_ROUND(29) TF_ROUND(16) TF_ROUND(24)
    x0 += ks1; x1 += ks2 + 4u;
    TF_ROUND(13) TF_ROUND(15) TF_ROUND(26) TF_ROUND(6)
    x0 += ks2; x1 += ks0 + 5u;
#undef TF_ROUND
    return make_uint2(x0, x1);
}

// ---------------- K1: IoU max/argmax + key + bucket append ----------------
__global__ void __launch_bounds__(TB) k_iou(const float* __restrict__ rois,
                                            const float* __restrict__ gtb) {
    __shared__ float4 sb[G];   // x1,y1,x2,y2
    __shared__ float  sa[G];   // area_b
    int tid = threadIdx.x;
    if (tid < G) {
        float x1 = gtb[tid * 4 + 0], y1 = gtb[tid * 4 + 1];
        float x2 = gtb[tid * 4 + 2], y2 = gtb[tid * 4 + 3];
        sb[tid] = make_float4(x1, y1, x2, y2);
        sa[tid] = __fmul_rn(x2 - x1 + 1.0f, y2 - y1 + 1.0f);
    }
    __syncthreads();

    int base = blockIdx.x * (TB * RPT) + tid;

    float ax1[RPT], ay1[RPT], ax2[RPT], ay2[RPT], aa[RPT], bn[RPT], bs[RPT];
    int bj[RPT];
#pragma unroll
    for (int r = 0; r < RPT; r++) {
        int i = base + r * TB;
        int ii = (i < NTOT) ? i : 0;
        if (ii < N_ROIS) {
            const float* p = rois + (size_t)ii * 5;
            ax1[r] = p[1]; ay1[r] = p[2]; ax2[r] = p[3]; ay2[r] = p[4];
        } else {
            const float* p = gtb + (size_t)(ii - N_ROIS) * 4;
            ax1[r] = p[0]; ay1[r] = p[1]; ax2[r] = p[2]; ay2[r] = p[3];
        }
        aa[r] = __fmul_rn(ax2[r] - ax1[r] + 1.0f, ay2[r] - ay1[r] + 1.0f);
        bn[r] = 0.0f; bs[r] = 1.0f; bj[r] = 0;
    }

#pragma unroll 4
    for (int j = 0; j < G; j++) {
        float4 b = sb[j];
        float  ab = sa[j];
#pragma unroll
        for (int r = 0; r < RPT; r++) {
            float xx1 = fmaxf(ax1[r], b.x);
            float yy1 = fmaxf(ay1[r], b.y);
            float xx2 = fminf(ax2[r], b.z);
            float yy2 = fminf(ay2[r], b.w);
            float iw = fmaxf(xx2 - xx1 + 1.0f, 0.0f);
            float ih = fmaxf(yy2 - yy1 + 1.0f, 0.0f);
            float inter = __fmul_rn(iw, ih);
            float S = aa[r] + ab;   // area_a + area_b (same rounding as reference)
            // iou ordering: inter/(S-inter) ordering == inter/S ordering (exact, S>0)
            if (__fmul_rn(inter, bs[r]) > __fmul_rn(bn[r], S)) {
                bn[r] = inter; bs[r] = S; bj[r] = j;
            }
        }
    }

#pragma unroll
    for (int r = 0; r < RPT; r++) {
        int i = base + r * TB;
        if (i >= NTOT) continue;
        // max overlap with reference rounding: denom = (area_a+area_b) - inter
        float mov = __fdiv_rn(bn[r], bs[r] - bn[r]);
        bool fg = (mov >= 0.5f);
        bool bg = (mov < 0.5f) && (mov >= 0.1f);
        if (fg || bg) {
            uint2 y = threefry42(0u, (unsigned)i);
            unsigned m = ((y.x ^ y.y) >> 9) + 1u;   // 1 .. 2^23, monotone in u
            unsigned long long rec =
                ((unsigned long long)m << 25) |
                ((unsigned long long)(0x3FFFFu - (unsigned)i) << 7) |
                (unsigned long long)(unsigned)bj[r];
            int sel = fg ? 0 : 1;
            unsigned bb = (m - 1u) >> 11;                 // 0..4095
            unsigned p = atomicAdd(&g_bcnt[sel][bb], 1u);
            if (p < CAP) g_bucket[sel][bb * CAP + p] = rec;
        }
    }
}

// ---------------- K2: select top-128, rank, and write ALL outputs ----------------
__global__ void __launch_bounds__(512) k_select(const float* __restrict__ rois,
                                                const float* __restrict__ gtb,
                                                const int* __restrict__ gtl,
                                                float* __restrict__ out) {
    __shared__ unsigned           swsum[16];
    __shared__ int                sB;
    __shared__ unsigned           sM;
    __shared__ int                s_nb;
    __shared__ int                s_dbin[128];
    __shared__ unsigned           s_dcnt[128];
    __shared__ unsigned           s_doff[128];
    __shared__ unsigned long long skey[512];
    __shared__ int                s_lab[128];
    __shared__ float              s_tgt[128][4];

    int sel = blockIdx.x;
    int t = threadIdx.x;
    int lane = t & 31, w = t >> 5;

    if (t == 0) { sB = 0; sM = 0u; s_nb = 0; }

    // 8 bins per thread
    unsigned loc[8];
    unsigned csum = 0;
#pragma unroll
    for (int k = 0; k < 8; k++) { loc[k] = g_bcnt[sel][t * 8 + k]; csum += loc[k]; }

    // warp suffix scan (inclusive from high lane): s = sum over lanes >= lane
    unsigned s = csum;
#pragma unroll
    for (int d = 1; d < 32; d <<= 1) {
        unsigned v = __shfl_down_sync(0xFFFFFFFFu, s, d);
        if (lane + d < 32) s += v;
    }
    if (lane == 0) swsum[w] = s;
    __syncthreads();

    // sum over higher warps (<=15 LDS, broadcast)
    unsigned wex = 0;
    for (int w2 = w + 1; w2 < 16; w2++) wex += swsum[w2];
    unsigned ex = wex + (s - csum);   // entries in bins strictly above my chunk

    // per-bin inclusive-from-top cumulative C(b)
    unsigned Carr[8];
    {
        unsigned suf = 0;
#pragma unroll
        for (int k = 7; k >= 0; k--) { suf += loc[k]; Carr[k] = ex + suf; }
    }

    // unique boundary bin: C(b) >= 128 and C(b+1) = C(b)-cnt(b) < 128 -> single writer
#pragma unroll
    for (int k = 0; k < 8; k++) {
        unsigned C = Carr[k];
        if (C >= 128u && (C - loc[k]) < 128u) { sB = t * 8 + k; sM = C; }
    }
    if (t == 0 && Carr[0] < 128u) sM = Carr[0];   // degenerate: fewer than 128 total

    // publish gather descriptors for bins >= B (done after barrier so B is final)
    __syncthreads();
    int B = sB;
    unsigned M = sM; if (M > 512u) M = 512u;

#pragma unroll
    for (int k = 0; k < 8; k++) {
        int bin = t * 8 + k;
        if (bin >= B && loc[k] > 0u) {
            int d = atomicAdd(&s_nb, 1);
            if (d < 128) {
                s_dbin[d] = bin;
                s_dcnt[d] = loc[k] < CAP ? loc[k] : CAP;
                s_doff[d] = Carr[k] - loc[k];   // position range [off, off+cnt)
            }
        }
    }
    __syncthreads();
    int nb = s_nb; if (nb > 128) nb = 128;

    // cooperative gather: all threads pull records in parallel
    for (unsigned e = t; e < M; e += 512) {
        unsigned long long v = 0ull;
        for (int d = 0; d < nb; d++) {
            unsigned off = s_doff[d];
            if (e >= off && e < off + s_dcnt[d]) {
                v = g_bucket[sel][(size_t)s_dbin[d] * CAP + (e - off)];
                break;
            }
        }
        skey[e] = v;
    }
    __syncthreads();

    // rank by counting (keys unique via embedded ~idx); rank 0 = largest
    int rank = -1;
    unsigned long long mykey = 0ull;
    if (t < (int)M) {
        mykey = skey[t];
        int r = 0;
        for (unsigned j = 0; j < M; j++) r += (skey[j] > mykey) ? 1 : 0;
        rank = r;
    }

    // ---- epilogue: row writes by rank ----
    bool emit = (rank >= 0 && rank < 128);
    bool pad  = (rank < 0 && t < 128 && (unsigned)t >= M);   // degenerate only
    if (emit || pad) {
        int r = emit ? rank : t;
        unsigned long long rec = emit ? mykey : 0ull;
        unsigned idx = 0x3FFFFu - (unsigned)((rec >> 7) & 0x3FFFFu);
        int ga = (int)(rec & 0x7Fu);
        if (idx >= NTOT) { idx = 0; ga = 0; }

        float c0, x1, y1, x2, y2;
        if (idx < N_ROIS) {
            const float* p = rois + (size_t)idx * 5;
            c0 = p[0]; x1 = p[1]; y1 = p[2]; x2 = p[3]; y2 = p[4];
        } else {
            const float* p = gtb + (size_t)(idx - N_ROIS) * 4;
            c0 = 0.0f; x1 = p[0]; y1 = p[1]; x2 = p[2]; y2 = p[3];
        }

        int rg = sel * 128 + r;   // global row 0..255
        // fg half: valid_fg always true (gt self-match guarantees >=128 fg)
        int label = (sel == 0) ? gtl[ga] : 0;
        s_lab[r] = label;

        out[rg * 5 + 0] = c0;
        out[rg * 5 + 1] = x1;
        out[rg * 5 + 2] = y1;
        out[rg * 5 + 3] = x2;
        out[rg * 5 + 4] = y2;
        out[1280 + rg] = (float)label;

        const float* g = gtb + (size_t)ga * 4;
        float ew = x2 - x1 + 1.0f, eh = y2 - y1 + 1.0f;
        float ecx = x1 + 0.5f * ew, ecy = y1 + 0.5f * eh;
        float gw = g[2] - g[0] + 1.0f, gh = g[3] - g[1] + 1.0f;
        float gcx = g[0] + 0.5f * gw, gcy = g[1] + 0.5f * gh;
        s_tgt[r][0] = (gcx - ecx) / ew;
        s_tgt[r][1] = (gcy - ecy) / eh;
        s_tgt[r][2] = logf(gw / ew);
        s_tgt[r][3] = logf(gh / eh);
    }
    __syncthreads();

    // ---- bbox_targets slab for this block's 128 rows: coalesced fill ----
    float* slab = out + 1536 + (size_t)sel * 128 * 84;
    for (int e = t; e < 128 * 84; e += 512) {
        int row = e / 84;
        int col = e - row * 84;
        int lab = s_lab[row];
        float v = 0.0f;
        int c0 = lab * 4;
        if (lab > 0 && col >= c0 && col < c0 + 4)
            v = s_tgt[row][col - c0];
        slab[e] = v;
    }

    // ---- re-zero this selector's bucket counters for the next replay ----
#pragma unroll
    for (int k = 0; k < 8; k++) g_bcnt[sel][t * 8 + k] = 0u;
}

// ---------------- launch ----------------
extern "C" void kernel_launch(void* const* d_in, const int* in_sizes, int n_in,
                              void* d_out, int out_size) {
    const float* all_rois = nullptr;  // 1,250,000 elems
    const float* gtb      = nullptr;  // 512 elems
    const int*   gtl      = nullptr;  // 128 elems
    for (int k = 0; k < n_in; k++) {
        if (in_sizes[k] == N_ROIS * 5) all_rois = (const float*)d_in[k];
        else if (in_sizes[k] == G * 4) gtb = (const float*)d_in[k];
        else if (in_sizes[k] == G)     gtl = (const int*)d_in[k];
    }
    float* out = (float*)d_out;

    k_iou<<<(NTOT + TB * RPT - 1) / (TB * RPT), TB>>>(all_rois, gtb);
    k_select<<<2, 512>>>(all_rois, gtb, gtl, out);
}